// round 14
// baseline (speedup 1.0000x reference)
#include <cuda_runtime.h>
#include <cuda_fp16.h>
#include <math.h>
#include <cstdint>

// Problem constants.
#define NN 65536
#define KK 8
#define HH 128
#define TT 4

#define NTF 16
#define GRID_F (NN / NTF + TT)      // 4100 forget-role blocks
#define NTI 64
#define GRID_I (NN / NTI + TT)      // 1028 iou-role blocks
#define TOTAL_BLOCKS (GRID_F + GRID_I)

// fp16 tile rows: 128 halves padded to 136 (272 bytes -> conflict-free).
#define ROWB 272

// ---- forget-role smem map (bytes): ~70.6KB -> 3 CTAs/SM ----
#define F_NODE 0
#define F_BF   64
#define F_A    1024
#define F_B    (F_A + 34816)
#define F_SMEM (F_B + 34816)

// ---- iou-role smem map (within same dynamic smem) ----
#define I_NODE 0
#define I_BST  512
#define I_A    2048
#define I_B    (I_A + 17408)

// ---------------- device scratch ----------------
__device__ int g_cnt[TT];
__device__ int g_cursor[TT];
__device__ int g_sorted[NN];
__device__ __half g_hsum[NN * HH];   // fp16 child-sum scratch (16 MB)
__device__ int g_flag[GRID_F];
__device__ int g_done;

// ---------------- helpers ----------------
__device__ __forceinline__ uint32_t smem_u32(const void* p) {
    uint32_t a;
    asm("{ .reg .u64 t; cvta.to.shared.u64 t, %1; cvt.u32.u64 %0, t; }" : "=r"(a) : "l"(p));
    return a;
}
__device__ __forceinline__ uint32_t h2u(float x, float y) {
    __half2 h = __floats2half2_rn(x, y);
    return *reinterpret_cast<uint32_t*>(&h);
}
__device__ __forceinline__ void pf_l2(const void* p) {
    asm volatile("prefetch.global.L2 [%0];" :: "l"(p));
}
__device__ __forceinline__ int ld_acq(const int* p) {
    int v;
    asm volatile("ld.acquire.gpu.global.b32 %0, [%1];" : "=r"(v) : "l"(p));
    return v;
}
__device__ __forceinline__ void st_rel(int* p, int v) {
    asm volatile("st.release.gpu.global.b32 [%0], %1;" :: "l"(p), "r"(v));
}
__device__ __forceinline__ void ldsm4(uint32_t* r, uint32_t a) {
    asm volatile("ldmatrix.sync.aligned.m8n8.x4.shared.b16 {%0,%1,%2,%3}, [%4];"
        : "=r"(r[0]), "=r"(r[1]), "=r"(r[2]), "=r"(r[3]) : "r"(a));
}
__device__ __forceinline__ void ldsm4t(uint32_t* r, uint32_t a) {
    asm volatile("ldmatrix.sync.aligned.m8n8.x4.trans.shared.b16 {%0,%1,%2,%3}, [%4];"
        : "=r"(r[0]), "=r"(r[1]), "=r"(r[2]), "=r"(r[3]) : "r"(a));
}
__device__ __forceinline__ void mma16(float* d, const uint32_t* a, uint32_t b0, uint32_t b1) {
    asm volatile("mma.sync.aligned.m16n8k16.row.col.f32.f16.f16.f32 "
        "{%0,%1,%2,%3}, {%4,%5,%6,%7}, {%8,%9}, {%0,%1,%2,%3};"
        : "+f"(d[0]), "+f"(d[1]), "+f"(d[2]), "+f"(d[3])
        : "r"(a[0]), "r"(a[1]), "r"(a[2]), "r"(a[3]), "r"(b0), "r"(b1));
}
__device__ __forceinline__ float sigm(float x) { return 1.f / (1.f + __expf(-x)); }

__device__ __forceinline__ void load_base(int* base) {
    int b = 0;
#pragma unroll
    for (int t = 0; t < TT; t++) { base[t] = b; b += g_cnt[t]; }
    base[TT] = b;
}

__device__ __forceinline__ bool find_chunk(int b, int NT, const int* base,
                                           int& t, int& rowstart, int& cnt) {
    int cb = 0;
#pragma unroll
    for (int tt = 0; tt < TT; tt++) {
        int lo = base[tt], hi = base[tt + 1];
        int ch = (hi - lo + NT - 1) / NT;
        if (b >= cb && b < cb + ch) {
            t = tt;
            rowstart = lo + (b - cb) * NT;
            cnt = min(NT, hi - rowstart);
            return true;
        }
        cb += ch;
    }
    return false;
}

// ---------------- partition: histogram (g_cnt pre-zeroed by previous cleanup) ----------------
__global__ void k_part1(const int* __restrict__ type_id) {
    __shared__ int sc[TT];
    if (threadIdx.x < TT) sc[threadIdx.x] = 0;
    __syncthreads();
    int i = blockIdx.x * 256 + threadIdx.x;
    int4 v = ((const int4*)type_id)[i];
    atomicAdd(&sc[v.x], 1);
    atomicAdd(&sc[v.y], 1);
    atomicAdd(&sc[v.z], 1);
    atomicAdd(&sc[v.w], 1);
    __syncthreads();
    if (threadIdx.x < TT) atomicAdd(&g_cnt[threadIdx.x], sc[threadIdx.x]);
}

__global__ void k_scatter(const int* __restrict__ type_id) {
    __shared__ int w_off[8][TT];
    __shared__ int blk_base[TT];
    int base[TT + 1];
    load_base(base);
    int n = blockIdx.x * 256 + threadIdx.x;
    int t = type_id[n];
    int w = threadIdx.x >> 5, lane = threadIdx.x & 31;
    int rank = 0;
#pragma unroll
    for (int tt = 0; tt < TT; tt++) {
        unsigned bm = __ballot_sync(0xffffffffu, t == tt);
        if (lane == 0) w_off[w][tt] = __popc(bm);
        if (t == tt) rank = __popc(bm & ((1u << lane) - 1));
    }
    __syncthreads();
    if (threadIdx.x < TT) {
        int tt = threadIdx.x, s = 0;
#pragma unroll
        for (int ww = 0; ww < 8; ww++) { int v = w_off[ww][tt]; w_off[ww][tt] = s; s += v; }
        blk_base[tt] = base[tt] + atomicAdd(&g_cursor[tt], s);
    }
    __syncthreads();
    g_sorted[blk_base[t] + w_off[w][t] + rank] = n;
}

// ---------------- forget role ----------------
__device__ __forceinline__ void forget_role(
    int fb, const int* base, char* smem, uint32_t sb, int tid, int wid, int lane,
    const float* __restrict__ h, const float* __restrict__ c,
    const float* __restrict__ f_input, const float* __restrict__ U_f,
    const float* __restrict__ b_f, float* __restrict__ out)
{
    int t, rowstart, cnt;
    if (!find_chunk(fb, NTF, base, t, rowstart, cnt)) return;

    int* sh_node = (int*)(smem + F_NODE);
    float* sbf = (float*)(smem + F_BF);
    if (tid < NTF) sh_node[tid] = g_sorted[rowstart + min(tid, cnt - 1)];
    if (tid >= 128) sbf[tid - 128] = b_f[t * HH + (tid - 128)];
    __syncthreads();

    const int node0 = wid * 2, node1 = node0 + 1;
    const int nd0 = sh_node[node0], nd1 = sh_node[node1];

    // L2 prefetch for this warp's epilogue streams.
    {
        const float* cA = c + (size_t)nd0 * KK * HH;
        const float* cB = c + (size_t)nd1 * KK * HH;
        pf_l2(cA + lane * 32);
        pf_l2(cB + lane * 32);
        if (lane < 4) {
            pf_l2(f_input + (size_t)nd0 * HH + lane * 32);
            pf_l2(f_input + (size_t)nd1 * HH + lane * 32);
        }
    }

    // A loader + fp16 hsum.
#pragma unroll
    for (int i = 0; i < 2; i++) {
        int task = tid + 256 * i;
        int j4 = task & 31, n = task >> 5;
        int nd = sh_node[n];
        float4 s = make_float4(0.f, 0.f, 0.f, 0.f);
#pragma unroll
        for (int ch = 0; ch < KK; ch++) {
            float4 v = *(const float4*)&h[((size_t)nd * KK + ch) * HH + j4 * 4];
            s.x += v.x; s.y += v.y; s.z += v.z; s.w += v.w;
            *(uint2*)(smem + F_A + (n * KK + ch) * ROWB + j4 * 8) =
                make_uint2(h2u(v.x, v.y), h2u(v.z, v.w));
        }
        *(uint2*)&g_hsum[(size_t)nd * HH + j4 * 4] = make_uint2(h2u(s.x, s.y), h2u(s.z, s.w));
    }
    // B loader: B[k][n] from U_f[t][k][n].
#pragma unroll
    for (int i = 0; i < 16; i++) {
        int task = tid + 256 * i;
        int n4 = task & 31, k = task >> 5;
        float4 v = *(const float4*)&U_f[(size_t)t * HH * HH + (size_t)k * HH + n4 * 4];
        *(uint2*)(smem + F_B + k * ROWB + n4 * 8) = make_uint2(h2u(v.x, v.y), h2u(v.z, v.w));
    }
    __threadfence();   // publish hsum gpu-wide before flag release
    __syncthreads();
    if (tid == 0) st_rel(&g_flag[fb], 1);

    // Preload all A fragments.
    const int m0 = wid * 16;
    const uint32_t aaddr = sb + F_A + (m0 + (lane & 15)) * ROWB + ((lane >> 4) << 4);
    uint32_t af[8][4];
#pragma unroll
    for (int ks = 0; ks < 8; ks++) ldsm4(af[ks], aaddr + ks * 32);

    const int klocal = (lane & 7) + ((lane >> 3) & 1) * 8;
    const uint32_t btaddr = sb + F_B + klocal * ROWB + (lane >> 4) * 16;

    const int child = lane >> 2, q = lane & 3;
    const float* c0p = c + ((size_t)nd0 * KK + child) * HH;
    const float* c1p = c + ((size_t)nd1 * KK + child) * HH;
    const float* f0p = f_input + (size_t)nd0 * HH;
    const float* f1p = f_input + (size_t)nd1 * HH;

#pragma unroll 1
    for (int nb = 0; nb < 8; nb++) {
        const int colbase = nb * 16 + 2 * q;
        float2 cv00 = *(const float2*)(c0p + colbase);
        float2 cv01 = *(const float2*)(c0p + colbase + 8);
        float2 cv10 = *(const float2*)(c1p + colbase);
        float2 cv11 = *(const float2*)(c1p + colbase + 8);
        float2 f00 = *(const float2*)(f0p + colbase);
        float2 f01 = *(const float2*)(f0p + colbase + 8);
        float2 f10 = *(const float2*)(f1p + colbase);
        float2 f11 = *(const float2*)(f1p + colbase + 8);

        float acc0[4] = {0.f, 0.f, 0.f, 0.f};
        float acc1[4] = {0.f, 0.f, 0.f, 0.f};
#pragma unroll
        for (int ks = 0; ks < 8; ks++) {
            uint32_t bf4[4];
            ldsm4t(bf4, btaddr + ks * 16 * ROWB + nb * 32);
            mma16(acc0, af[ks], bf4[0], bf4[1]);
            mma16(acc1, af[ks], bf4[2], bf4[3]);
        }

        float2 bf0 = *(float2*)&sbf[colbase];
        float2 bf1 = *(float2*)&sbf[colbase + 8];

        float v00 = sigm(acc0[0] + f00.x + bf0.x) * cv00.x;
        float v01 = sigm(acc0[1] + f00.y + bf0.y) * cv00.y;
        float v10 = sigm(acc0[2] + f10.x + bf0.x) * cv10.x;
        float v11 = sigm(acc0[3] + f10.y + bf0.y) * cv10.y;
        float w00 = sigm(acc1[0] + f01.x + bf1.x) * cv01.x;
        float w01 = sigm(acc1[1] + f01.y + bf1.y) * cv01.y;
        float w10 = sigm(acc1[2] + f11.x + bf1.x) * cv11.x;
        float w11 = sigm(acc1[3] + f11.y + bf1.y) * cv11.y;
#pragma unroll
        for (int d = 4; d < 32; d <<= 1) {
            v00 += __shfl_xor_sync(0xffffffffu, v00, d);
            v01 += __shfl_xor_sync(0xffffffffu, v01, d);
            v10 += __shfl_xor_sync(0xffffffffu, v10, d);
            v11 += __shfl_xor_sync(0xffffffffu, v11, d);
            w00 += __shfl_xor_sync(0xffffffffu, w00, d);
            w01 += __shfl_xor_sync(0xffffffffu, w01, d);
            w10 += __shfl_xor_sync(0xffffffffu, w10, d);
            w11 += __shfl_xor_sync(0xffffffffu, w11, d);
        }
        if (lane < 4 && node0 < cnt) {
            *(float2*)&out[(size_t)nd0 * 512 + 384 + nb * 16 + 2 * lane] = make_float2(v00, v01);
            *(float2*)&out[(size_t)nd0 * 512 + 384 + nb * 16 + 8 + 2 * lane] = make_float2(w00, w01);
        }
        if (lane >= 4 && lane < 8 && node1 < cnt) {
            *(float2*)&out[(size_t)nd1 * 512 + 384 + nb * 16 + 2 * (lane - 4)] = make_float2(v10, v11);
            *(float2*)&out[(size_t)nd1 * 512 + 384 + nb * 16 + 8 + 2 * (lane - 4)] = make_float2(w10, w11);
        }
    }
}

// ---------------- iou role ----------------
__device__ __forceinline__ void iou_role(
    int ib, const int* base, char* smem, uint32_t sb, int tid, int wid, int lane,
    const float* __restrict__ U_iou, const float* __restrict__ b_iou,
    float* __restrict__ out)
{
    int t, rowstart, cnt;
    if (!find_chunk(ib, NTI, base, t, rowstart, cnt)) return;

    // Wait for producing forget chunks.
    {
        int cbF = 0;
#pragma unroll
        for (int tt = 0; tt < TT; tt++) {
            if (tt == t) break;
            cbF += (base[tt + 1] - base[tt] + NTF - 1) / NTF;
        }
        int lo = base[t];
        int bstart = cbF + (rowstart - lo) / NTF;
        int bend = cbF + (rowstart + cnt - 1 - lo) / NTF;
        if (tid <= bend - bstart) {
            const int* fp = &g_flag[bstart + tid];
            while (ld_acq(fp) == 0) { __nanosleep(64); }
        }
    }
    __syncthreads();

    int* sh_node = (int*)(smem + I_NODE);
    float* bst = (float*)(smem + I_BST);
    if (tid < 64) sh_node[tid] = g_sorted[rowstart + min(tid, cnt - 1)];
    if (tid < 128) {
        bst[tid] = b_iou[t * 384 + tid];
        bst[128 + tid] = b_iou[t * 384 + 128 + tid];
        bst[256 + tid] = b_iou[t * 384 + 256 + tid];
    }
    __syncthreads();

    // A loader: [64 m][128 k] fp16 straight from g_hsum (already fp16).
#pragma unroll
    for (int i = 0; i < 4; i++) {
        int task = tid + 256 * i;
        int m = task >> 4, j8 = task & 15;
        uint4 v = __ldcg((const uint4*)&g_hsum[(size_t)sh_node[m] * HH + j8 * 8]);
        *(uint4*)(smem + I_A + m * ROWB + j8 * 16) = v;
    }
    __syncthreads();

    const int m0 = (wid >> 1) * 16;
    const int nh = wid & 1;
    const uint32_t aaddr = sb + I_A + (m0 + (lane & 15)) * ROWB + ((lane >> 4) << 4);
    uint32_t af[8][4];
#pragma unroll
    for (int ks = 0; ks < 8; ks++) ldsm4(af[ks], aaddr + ks * 32);

    const int klocal = (lane & 7) + ((lane >> 3) & 1) * 8;
    const uint32_t btaddr = sb + I_B + klocal * ROWB + (lane >> 4) * 16 + nh * 128;
    const int r0 = m0 + (lane >> 2), r1 = r0 + 8;
    const int q = lane & 3;
    const int nr0 = sh_node[r0], nr1 = sh_node[r1];

    for (int nc = 0; nc < 3; nc++) {
        if (nc > 0) __syncthreads();
#pragma unroll
        for (int i = 0; i < 16; i++) {
            int task = tid + 256 * i;
            int n4 = task & 31, k = task >> 5;
            float4 v = *(const float4*)&U_iou[(size_t)t * HH * 384 + (size_t)k * 384 + nc * 128 + n4 * 4];
            *(uint2*)(smem + I_B + k * ROWB + n4 * 8) = make_uint2(h2u(v.x, v.y), h2u(v.z, v.w));
        }
        __syncthreads();

#pragma unroll 1
        for (int nb = 0; nb < 4; nb++) {
            float acc0[4] = {0.f, 0.f, 0.f, 0.f};
            float acc1[4] = {0.f, 0.f, 0.f, 0.f};
#pragma unroll
            for (int ks = 0; ks < 8; ks++) {
                uint32_t bf4[4];
                ldsm4t(bf4, btaddr + ks * 16 * ROWB + nb * 32);
                mma16(acc0, af[ks], bf4[0], bf4[1]);
                mma16(acc1, af[ks], bf4[2], bf4[3]);
            }
            const int colbase = nh * 64 + nb * 16 + 2 * q;
            float2 b20 = *(float2*)&bst[nc * 128 + colbase];
            float2 b21 = *(float2*)&bst[nc * 128 + colbase + 8];
            if (r0 < cnt) {
                *(float2*)&out[(size_t)nr0 * 512 + nc * 128 + colbase] =
                    make_float2(acc0[0] + b20.x, acc0[1] + b20.y);
                *(float2*)&out[(size_t)nr0 * 512 + nc * 128 + colbase + 8] =
                    make_float2(acc1[0] + b21.x, acc1[1] + b21.y);
            }
            if (r1 < cnt) {
                *(float2*)&out[(size_t)nr1 * 512 + nc * 128 + colbase] =
                    make_float2(acc0[2] + b20.x, acc0[3] + b20.y);
                *(float2*)&out[(size_t)nr1 * 512 + nc * 128 + colbase + 8] =
                    make_float2(acc1[2] + b21.x, acc1[3] + b21.y);
            }
        }
    }
}

// ---------------- merged kernel + state cleanup ----------------
__global__ __launch_bounds__(256, 3) void k_main(
    const float* __restrict__ h, const float* __restrict__ c,
    const float* __restrict__ f_input,
    const float* __restrict__ U_iou, const float* __restrict__ b_iou,
    const float* __restrict__ U_f, const float* __restrict__ b_f,
    float* __restrict__ out)
{
    extern __shared__ __align__(1024) char smem[];
    static __shared__ int s_last;
    const uint32_t sb = smem_u32(smem);
    const int tid = threadIdx.x, wid = tid >> 5, lane = tid & 31;

    int base[TT + 1];
    load_base(base);

    if (blockIdx.x < GRID_F)
        forget_role(blockIdx.x, base, smem, sb, tid, wid, lane, h, c, f_input, U_f, b_f, out);
    else
        iou_role(blockIdx.x - GRID_F, base, smem, sb, tid, wid, lane, U_iou, b_iou, out);

    // Last-block cleanup: restore zeroed scratch for the next graph replay.
    __threadfence();
    __syncthreads();
    if (tid == 0) s_last = (atomicAdd(&g_done, 1) == TOTAL_BLOCKS - 1);
    __syncthreads();
    if (s_last) {
        for (int i = tid; i < GRID_F; i += 256) g_flag[i] = 0;
        if (tid < TT) { g_cnt[tid] = 0; g_cursor[tid] = 0; }
        __threadfence();
        __syncthreads();
        if (tid == 0) g_done = 0;
    }
}

// ---------------- launch ----------------
extern "C" void kernel_launch(void* const* d_in, const int* in_sizes, int n_in,
                              void* d_out, int out_size) {
    const float* h       = (const float*)d_in[0];
    const float* c       = (const float*)d_in[1];
    const float* f_input = (const float*)d_in[2];
    const int*   type_id = (const int*)d_in[3];
    const float* U_iou   = (const float*)d_in[4];
    const float* b_iou   = (const float*)d_in[5];
    const float* U_f     = (const float*)d_in[6];
    const float* b_f     = (const float*)d_in[7];
    float* out = (float*)d_out;

    static int attr_done = 0;
    if (!attr_done) {
        cudaFuncSetAttribute(k_main, cudaFuncAttributeMaxDynamicSharedMemorySize, F_SMEM);
        attr_done = 1;
    }

    k_part1<<<NN / 1024, 256>>>(type_id);
    k_scatter<<<NN / 256, 256>>>(type_id);
    k_main<<<TOTAL_BLOCKS, 256, F_SMEM>>>(h, c, f_input, U_iou, b_iou, U_f, b_f, out);
}

// round 15
// speedup vs baseline: 1.2046x; 1.2046x over previous
#include <cuda_runtime.h>
#include <cuda_fp16.h>
#include <math.h>
#include <cstdint>

// Problem constants.
#define NN 65536
#define KK 8
#define HH 128
#define TT 4

#define NTF 16
#define GRID_F (NN / NTF + TT)      // 4100 forget-role blocks
#define NTI 64
#define GRID_I (NN / NTI + TT)      // 1028 iou-role blocks

// fp16 tile rows: 128 halves padded to 136 (272 bytes -> conflict-free).
#define ROWB 272

// ---- forget-role smem map (bytes): ~70.6KB -> 3 CTAs/SM ----
#define F_NODE 0
#define F_BF   64
#define F_A    1024
#define F_B    (F_A + 34816)
#define F_SMEM (F_B + 34816)

// ---- iou-role smem map (within same dynamic smem) ----
#define I_NODE 0
#define I_BST  512
#define I_A    2048
#define I_B    (I_A + 17408)

// ---------------- device scratch ----------------
__device__ int g_cnt[TT];
__device__ int g_base[TT + 1];
__device__ int g_cursor[TT];
__device__ int g_sorted[NN];
__device__ __half g_hsum[NN * HH];   // fp16 child-sum scratch
__device__ int g_flag[GRID_F];

// ---------------- helpers ----------------
__device__ __forceinline__ uint32_t smem_u32(const void* p) {
    uint32_t a;
    asm("{ .reg .u64 t; cvta.to.shared.u64 t, %1; cvt.u32.u64 %0, t; }" : "=r"(a) : "l"(p));
    return a;
}
__device__ __forceinline__ uint32_t h2u(float x, float y) {
    __half2 h = __floats2half2_rn(x, y);
    return *reinterpret_cast<uint32_t*>(&h);
}
__device__ __forceinline__ void pf_l2(const void* p) {
    asm volatile("prefetch.global.L2 [%0];" :: "l"(p));
}
__device__ __forceinline__ int ld_acq(const int* p) {
    int v;
    asm volatile("ld.acquire.gpu.global.b32 %0, [%1];" : "=r"(v) : "l"(p));
    return v;
}
__device__ __forceinline__ void st_rel(int* p, int v) {
    asm volatile("st.release.gpu.global.b32 [%0], %1;" :: "l"(p), "r"(v));
}
__device__ __forceinline__ void ldsm4(uint32_t* r, uint32_t a) {
    asm volatile("ldmatrix.sync.aligned.m8n8.x4.shared.b16 {%0,%1,%2,%3}, [%4];"
        : "=r"(r[0]), "=r"(r[1]), "=r"(r[2]), "=r"(r[3]) : "r"(a));
}
__device__ __forceinline__ void ldsm4t(uint32_t* r, uint32_t a) {
    asm volatile("ldmatrix.sync.aligned.m8n8.x4.trans.shared.b16 {%0,%1,%2,%3}, [%4];"
        : "=r"(r[0]), "=r"(r[1]), "=r"(r[2]), "=r"(r[3]) : "r"(a));
}
__device__ __forceinline__ void mma16(float* d, const uint32_t* a, uint32_t b0, uint32_t b1) {
    asm volatile("mma.sync.aligned.m16n8k16.row.col.f32.f16.f16.f32 "
        "{%0,%1,%2,%3}, {%4,%5,%6,%7}, {%8,%9}, {%0,%1,%2,%3};"
        : "+f"(d[0]), "+f"(d[1]), "+f"(d[2]), "+f"(d[3])
        : "r"(a[0]), "r"(a[1]), "r"(a[2]), "r"(a[3]), "r"(b0), "r"(b1));
}
// sigmoid via single-MUFU tanh.approx: sigmoid(x) = 0.5*tanh(x/2) + 0.5
__device__ __forceinline__ float sigm(float x) {
    float t;
    asm("tanh.approx.f32 %0, %1;" : "=f"(t) : "f"(x * 0.5f));
    return fmaf(0.5f, t, 0.5f);
}

__device__ __forceinline__ bool find_chunk(int b, int NT, int& t, int& rowstart, int& cnt) {
    int cb = 0;
#pragma unroll
    for (int tt = 0; tt < TT; tt++) {
        int lo = g_base[tt], hi = g_base[tt + 1];
        int ch = (hi - lo + NT - 1) / NT;
        if (b >= cb && b < cb + ch) {
            t = tt;
            rowstart = lo + (b - cb) * NT;
            cnt = min(NT, hi - rowstart);
            return true;
        }
        cb += ch;
    }
    return false;
}

// ---------------- partition pipeline ----------------
__global__ void k_zero() {
    int i = blockIdx.x * 256 + threadIdx.x;
    if (i < GRID_F) g_flag[i] = 0;
    if (i < TT) g_cnt[i] = 0;
}
__global__ void k_hist(const int* __restrict__ type_id) {
    __shared__ int sc[TT];
    if (threadIdx.x < TT) sc[threadIdx.x] = 0;
    __syncthreads();
    int i = blockIdx.x * 256 + threadIdx.x;
    int4 v = ((const int4*)type_id)[i];
    atomicAdd(&sc[v.x], 1);
    atomicAdd(&sc[v.y], 1);
    atomicAdd(&sc[v.z], 1);
    atomicAdd(&sc[v.w], 1);
    __syncthreads();
    if (threadIdx.x < TT) atomicAdd(&g_cnt[threadIdx.x], sc[threadIdx.x]);
}
__global__ void k_scan() {
    int b = 0;
#pragma unroll
    for (int t = 0; t < TT; t++) { g_base[t] = b; g_cursor[t] = b; b += g_cnt[t]; }
    g_base[TT] = b;
}
__global__ void k_scatter(const int* __restrict__ type_id) {
    __shared__ int w_off[8][TT];
    __shared__ int blk_base[TT];
    int n = blockIdx.x * 256 + threadIdx.x;
    int t = type_id[n];
    int w = threadIdx.x >> 5, lane = threadIdx.x & 31;
    int rank = 0;
#pragma unroll
    for (int tt = 0; tt < TT; tt++) {
        unsigned bm = __ballot_sync(0xffffffffu, t == tt);
        if (lane == 0) w_off[w][tt] = __popc(bm);
        if (t == tt) rank = __popc(bm & ((1u << lane) - 1));
    }
    __syncthreads();
    if (threadIdx.x < TT) {
        int tt = threadIdx.x, s = 0;
#pragma unroll
        for (int ww = 0; ww < 8; ww++) { int v = w_off[ww][tt]; w_off[ww][tt] = s; s += v; }
        blk_base[tt] = atomicAdd(&g_cursor[tt], s);
    }
    __syncthreads();
    g_sorted[blk_base[t] + w_off[w][t] + rank] = n;
}

// ---------------- forget role ----------------
__device__ __forceinline__ void forget_role(
    int fb, char* smem, uint32_t sb, int tid, int wid, int lane,
    const float* __restrict__ h, const float* __restrict__ c,
    const float* __restrict__ f_input, const float* __restrict__ U_f,
    const float* __restrict__ b_f, float* __restrict__ out)
{
    int t, rowstart, cnt;
    if (!find_chunk(fb, NTF, t, rowstart, cnt)) return;

    int* sh_node = (int*)(smem + F_NODE);
    float* sbf = (float*)(smem + F_BF);
    if (tid < NTF) sh_node[tid] = g_sorted[rowstart + min(tid, cnt - 1)];
    if (tid >= 128) sbf[tid - 128] = b_f[t * HH + (tid - 128)];
    __syncthreads();

    const int node0 = wid * 2, node1 = node0 + 1;
    const int nd0 = sh_node[node0], nd1 = sh_node[node1];

    // L2 prefetch for this warp's epilogue streams.
    {
        const float* cA = c + (size_t)nd0 * KK * HH;
        const float* cB = c + (size_t)nd1 * KK * HH;
        pf_l2(cA + lane * 32);
        pf_l2(cB + lane * 32);
        if (lane < 4) {
            pf_l2(f_input + (size_t)nd0 * HH + lane * 32);
            pf_l2(f_input + (size_t)nd1 * HH + lane * 32);
        }
    }

    // A loader + fp16 hsum.
#pragma unroll
    for (int i = 0; i < 2; i++) {
        int task = tid + 256 * i;
        int j4 = task & 31, n = task >> 5;
        int nd = sh_node[n];
        float4 s = make_float4(0.f, 0.f, 0.f, 0.f);
#pragma unroll
        for (int ch = 0; ch < KK; ch++) {
            float4 v = *(const float4*)&h[((size_t)nd * KK + ch) * HH + j4 * 4];
            s.x += v.x; s.y += v.y; s.z += v.z; s.w += v.w;
            *(uint2*)(smem + F_A + (n * KK + ch) * ROWB + j4 * 8) =
                make_uint2(h2u(v.x, v.y), h2u(v.z, v.w));
        }
        *(uint2*)&g_hsum[(size_t)nd * HH + j4 * 4] = make_uint2(h2u(s.x, s.y), h2u(s.z, s.w));
    }
    // B loader: B[k][n] from U_f[t][k][n].
#pragma unroll
    for (int i = 0; i < 16; i++) {
        int task = tid + 256 * i;
        int n4 = task & 31, k = task >> 5;
        float4 v = *(const float4*)&U_f[(size_t)t * HH * HH + (size_t)k * HH + n4 * 4];
        *(uint2*)(smem + F_B + k * ROWB + n4 * 8) = make_uint2(h2u(v.x, v.y), h2u(v.z, v.w));
    }
    __threadfence();   // publish hsum gpu-wide before flag release
    __syncthreads();
    if (tid == 0) st_rel(&g_flag[fb], 1);

    // Preload all A fragments.
    const int m0 = wid * 16;
    const uint32_t aaddr = sb + F_A + (m0 + (lane & 15)) * ROWB + ((lane >> 4) << 4);
    uint32_t af[8][4];
#pragma unroll
    for (int ks = 0; ks < 8; ks++) ldsm4(af[ks], aaddr + ks * 32);

    const int klocal = (lane & 7) + ((lane >> 3) & 1) * 8;
    const uint32_t btaddr = sb + F_B + klocal * ROWB + (lane >> 4) * 16;

    const int child = lane >> 2, q = lane & 3;
    const float* c0p = c + ((size_t)nd0 * KK + child) * HH;
    const float* c1p = c + ((size_t)nd1 * KK + child) * HH;
    const float* f0p = f_input + (size_t)nd0 * HH;
    const float* f1p = f_input + (size_t)nd1 * HH;

#pragma unroll 1
    for (int nb = 0; nb < 8; nb++) {
        const int colbase = nb * 16 + 2 * q;
        float2 cv00 = *(const float2*)(c0p + colbase);
        float2 cv01 = *(const float2*)(c0p + colbase + 8);
        float2 cv10 = *(const float2*)(c1p + colbase);
        float2 cv11 = *(const float2*)(c1p + colbase + 8);
        float2 f00 = *(const float2*)(f0p + colbase);
        float2 f01 = *(const float2*)(f0p + colbase + 8);
        float2 f10 = *(const float2*)(f1p + colbase);
        float2 f11 = *(const float2*)(f1p + colbase + 8);

        float acc0[4] = {0.f, 0.f, 0.f, 0.f};
        float acc1[4] = {0.f, 0.f, 0.f, 0.f};
#pragma unroll
        for (int ks = 0; ks < 8; ks++) {
            uint32_t bf4[4];
            ldsm4t(bf4, btaddr + ks * 16 * ROWB + nb * 32);
            mma16(acc0, af[ks], bf4[0], bf4[1]);
            mma16(acc1, af[ks], bf4[2], bf4[3]);
        }

        float2 bf0 = *(float2*)&sbf[colbase];
        float2 bf1 = *(float2*)&sbf[colbase + 8];

        float v00 = sigm(acc0[0] + f00.x + bf0.x) * cv00.x;
        float v01 = sigm(acc0[1] + f00.y + bf0.y) * cv00.y;
        float v10 = sigm(acc0[2] + f10.x + bf0.x) * cv10.x;
        float v11 = sigm(acc0[3] + f10.y + bf0.y) * cv10.y;
        float w00 = sigm(acc1[0] + f01.x + bf1.x) * cv01.x;
        float w01 = sigm(acc1[1] + f01.y + bf1.y) * cv01.y;
        float w10 = sigm(acc1[2] + f11.x + bf1.x) * cv11.x;
        float w11 = sigm(acc1[3] + f11.y + bf1.y) * cv11.y;
#pragma unroll
        for (int d = 4; d < 32; d <<= 1) {
            v00 += __shfl_xor_sync(0xffffffffu, v00, d);
            v01 += __shfl_xor_sync(0xffffffffu, v01, d);
            v10 += __shfl_xor_sync(0xffffffffu, v10, d);
            v11 += __shfl_xor_sync(0xffffffffu, v11, d);
            w00 += __shfl_xor_sync(0xffffffffu, w00, d);
            w01 += __shfl_xor_sync(0xffffffffu, w01, d);
            w10 += __shfl_xor_sync(0xffffffffu, w10, d);
            w11 += __shfl_xor_sync(0xffffffffu, w11, d);
        }
        if (lane < 4 && node0 < cnt) {
            *(float2*)&out[(size_t)nd0 * 512 + 384 + nb * 16 + 2 * lane] = make_float2(v00, v01);
            *(float2*)&out[(size_t)nd0 * 512 + 384 + nb * 16 + 8 + 2 * lane] = make_float2(w00, w01);
        }
        if (lane >= 4 && lane < 8 && node1 < cnt) {
            *(float2*)&out[(size_t)nd1 * 512 + 384 + nb * 16 + 2 * (lane - 4)] = make_float2(v10, v11);
            *(float2*)&out[(size_t)nd1 * 512 + 384 + nb * 16 + 8 + 2 * (lane - 4)] = make_float2(w10, w11);
        }
    }
}

// ---------------- iou role ----------------
__device__ __forceinline__ void iou_role(
    int ib, char* smem, uint32_t sb, int tid, int wid, int lane,
    const float* __restrict__ U_iou, const float* __restrict__ b_iou,
    float* __restrict__ out)
{
    int t, rowstart, cnt;
    if (!find_chunk(ib, NTI, t, rowstart, cnt)) return;

    // Wait for producing forget chunks.
    {
        int cbF = 0;
#pragma unroll
        for (int tt = 0; tt < TT; tt++) {
            if (tt == t) break;
            cbF += (g_base[tt + 1] - g_base[tt] + NTF - 1) / NTF;
        }
        int lo = g_base[t];
        int bstart = cbF + (rowstart - lo) / NTF;
        int bend = cbF + (rowstart + cnt - 1 - lo) / NTF;
        if (tid <= bend - bstart) {
            const int* fp = &g_flag[bstart + tid];
            while (ld_acq(fp) == 0) { __nanosleep(64); }
        }
    }
    __syncthreads();

    int* sh_node = (int*)(smem + I_NODE);
    float* bst = (float*)(smem + I_BST);
    if (tid < 64) sh_node[tid] = g_sorted[rowstart + min(tid, cnt - 1)];
    if (tid < 128) {
        bst[tid] = b_iou[t * 384 + tid];
        bst[128 + tid] = b_iou[t * 384 + 128 + tid];
        bst[256 + tid] = b_iou[t * 384 + 256 + tid];
    }
    __syncthreads();

    // A loader: [64 m][128 k] straight fp16 copy from g_hsum.
#pragma unroll
    for (int i = 0; i < 4; i++) {
        int task = tid + 256 * i;
        int m = task >> 4, j8 = task & 15;
        uint4 v = __ldcg((const uint4*)&g_hsum[(size_t)sh_node[m] * HH + j8 * 8]);
        *(uint4*)(smem + I_A + m * ROWB + j8 * 16) = v;
    }
    __syncthreads();

    const int m0 = (wid >> 1) * 16;
    const int nh = wid & 1;
    const uint32_t aaddr = sb + I_A + (m0 + (lane & 15)) * ROWB + ((lane >> 4) << 4);
    uint32_t af[8][4];
#pragma unroll
    for (int ks = 0; ks < 8; ks++) ldsm4(af[ks], aaddr + ks * 32);

    const int klocal = (lane & 7) + ((lane >> 3) & 1) * 8;
    const uint32_t btaddr = sb + I_B + klocal * ROWB + (lane >> 4) * 16 + nh * 128;
    const int r0 = m0 + (lane >> 2), r1 = r0 + 8;
    const int q = lane & 3;
    const int nr0 = sh_node[r0], nr1 = sh_node[r1];

    for (int nc = 0; nc < 3; nc++) {
        if (nc > 0) __syncthreads();
#pragma unroll
        for (int i = 0; i < 16; i++) {
            int task = tid + 256 * i;
            int n4 = task & 31, k = task >> 5;
            float4 v = *(const float4*)&U_iou[(size_t)t * HH * 384 + (size_t)k * 384 + nc * 128 + n4 * 4];
            *(uint2*)(smem + I_B + k * ROWB + n4 * 8) = make_uint2(h2u(v.x, v.y), h2u(v.z, v.w));
        }
        __syncthreads();

#pragma unroll 1
        for (int nb = 0; nb < 4; nb++) {
            float acc0[4] = {0.f, 0.f, 0.f, 0.f};
            float acc1[4] = {0.f, 0.f, 0.f, 0.f};
#pragma unroll
            for (int ks = 0; ks < 8; ks++) {
                uint32_t bf4[4];
                ldsm4t(bf4, btaddr + ks * 16 * ROWB + nb * 32);
                mma16(acc0, af[ks], bf4[0], bf4[1]);
                mma16(acc1, af[ks], bf4[2], bf4[3]);
            }
            const int colbase = nh * 64 + nb * 16 + 2 * q;
            float2 b20 = *(float2*)&bst[nc * 128 + colbase];
            float2 b21 = *(float2*)&bst[nc * 128 + colbase + 8];
            if (r0 < cnt) {
                *(float2*)&out[(size_t)nr0 * 512 + nc * 128 + colbase] =
                    make_float2(acc0[0] + b20.x, acc0[1] + b20.y);
                *(float2*)&out[(size_t)nr0 * 512 + nc * 128 + colbase + 8] =
                    make_float2(acc1[0] + b21.x, acc1[1] + b21.y);
            }
            if (r1 < cnt) {
                *(float2*)&out[(size_t)nr1 * 512 + nc * 128 + colbase] =
                    make_float2(acc0[2] + b20.x, acc0[3] + b20.y);
                *(float2*)&out[(size_t)nr1 * 512 + nc * 128 + colbase + 8] =
                    make_float2(acc1[2] + b21.x, acc1[3] + b21.y);
            }
        }
    }
}

// ---------------- merged kernel ----------------
__global__ __launch_bounds__(256, 3) void k_main(
    const float* __restrict__ h, const float* __restrict__ c,
    const float* __restrict__ f_input,
    const float* __restrict__ U_iou, const float* __restrict__ b_iou,
    const float* __restrict__ U_f, const float* __restrict__ b_f,
    float* __restrict__ out)
{
    extern __shared__ __align__(1024) char smem[];
    const uint32_t sb = smem_u32(smem);
    const int tid = threadIdx.x, wid = tid >> 5, lane = tid & 31;
    if (blockIdx.x < GRID_F)
        forget_role(blockIdx.x, smem, sb, tid, wid, lane, h, c, f_input, U_f, b_f, out);
    else
        iou_role(blockIdx.x - GRID_F, smem, sb, tid, wid, lane, U_iou, b_iou, out);
}

// ---------------- launch ----------------
extern "C" void kernel_launch(void* const* d_in, const int* in_sizes, int n_in,
                              void* d_out, int out_size) {
    const float* h       = (const float*)d_in[0];
    const float* c       = (const float*)d_in[1];
    const float* f_input = (const float*)d_in[2];
    const int*   type_id = (const int*)d_in[3];
    const float* U_iou   = (const float*)d_in[4];
    const float* b_iou   = (const float*)d_in[5];
    const float* U_f     = (const float*)d_in[6];
    const float* b_f     = (const float*)d_in[7];
    float* out = (float*)d_out;

    static int attr_done = 0;
    if (!attr_done) {
        cudaFuncSetAttribute(k_main, cudaFuncAttributeMaxDynamicSharedMemorySize, F_SMEM);
        attr_done = 1;
    }

    k_zero<<<(GRID_F + 255) / 256, 256>>>();
    k_hist<<<NN / 1024, 256>>>(type_id);
    k_scan<<<1, 1>>>();
    k_scatter<<<NN / 256, 256>>>(type_id);
    k_main<<<GRID_F + GRID_I, 256, F_SMEM>>>(h, c, f_input, U_iou, b_iou, U_f, b_f, out);
}

// round 16
// speedup vs baseline: 1.2163x; 1.0098x over previous
#include <cuda_runtime.h>
#include <cuda_fp16.h>
#include <math.h>
#include <cstdint>

// Problem constants.
#define NN 65536
#define KK 8
#define HH 128
#define TT 4

#define NTF 16
#define GRID_F (NN / NTF + TT)      // 4100 forget-role blocks
#define NTI 64
#define GRID_I (NN / NTI + TT)      // 1028 iou-role blocks
#define SCAT_BLOCKS (NN / 256)      // 256

// fp16 tile rows: 128 halves padded to 136 (272 bytes -> conflict-free).
#define ROWB 272

// ---- forget-role smem map (bytes): ~70.6KB -> 3 CTAs/SM ----
#define F_NODE 0
#define F_BF   64
#define F_A    1024
#define F_B    (F_A + 34816)
#define F_SMEM (F_B + 34816)

// ---- iou-role smem map (within same dynamic smem) ----
#define I_NODE 0
#define I_BST  512
#define I_A    2048
#define I_B    (I_A + 17408)

// ---------------- device scratch (zero-initialized at load) ----------------
__device__ int g_cnt[TT];
__device__ int g_base[TT + 1];
__device__ int g_cursor[TT];
__device__ int g_scat_done;
__device__ int g_sorted[NN];
__device__ __half g_hsum[NN * HH];   // fp16 child-sum scratch
__device__ int g_flag[GRID_F];

// ---------------- helpers ----------------
__device__ __forceinline__ uint32_t smem_u32(const void* p) {
    uint32_t a;
    asm("{ .reg .u64 t; cvta.to.shared.u64 t, %1; cvt.u32.u64 %0, t; }" : "=r"(a) : "l"(p));
    return a;
}
__device__ __forceinline__ uint32_t h2u(float x, float y) {
    __half2 h = __floats2half2_rn(x, y);
    return *reinterpret_cast<uint32_t*>(&h);
}
__device__ __forceinline__ void pf_l2(const void* p) {
    asm volatile("prefetch.global.L2 [%0];" :: "l"(p));
}
__device__ __forceinline__ int ld_acq(const int* p) {
    int v;
    asm volatile("ld.acquire.gpu.global.b32 %0, [%1];" : "=r"(v) : "l"(p));
    return v;
}
__device__ __forceinline__ void st_rel(int* p, int v) {
    asm volatile("st.release.gpu.global.b32 [%0], %1;" :: "l"(p), "r"(v));
}
__device__ __forceinline__ void ldsm4(uint32_t* r, uint32_t a) {
    asm volatile("ldmatrix.sync.aligned.m8n8.x4.shared.b16 {%0,%1,%2,%3}, [%4];"
        : "=r"(r[0]), "=r"(r[1]), "=r"(r[2]), "=r"(r[3]) : "r"(a));
}
__device__ __forceinline__ void ldsm4t(uint32_t* r, uint32_t a) {
    asm volatile("ldmatrix.sync.aligned.m8n8.x4.trans.shared.b16 {%0,%1,%2,%3}, [%4];"
        : "=r"(r[0]), "=r"(r[1]), "=r"(r[2]), "=r"(r[3]) : "r"(a));
}
__device__ __forceinline__ void mma16(float* d, const uint32_t* a, uint32_t b0, uint32_t b1) {
    asm volatile("mma.sync.aligned.m16n8k16.row.col.f32.f16.f16.f32 "
        "{%0,%1,%2,%3}, {%4,%5,%6,%7}, {%8,%9}, {%0,%1,%2,%3};"
        : "+f"(d[0]), "+f"(d[1]), "+f"(d[2]), "+f"(d[3])
        : "r"(a[0]), "r"(a[1]), "r"(a[2]), "r"(a[3]), "r"(b0), "r"(b1));
}
// sigmoid via single-MUFU tanh.approx: sigmoid(x) = 0.5*tanh(x/2) + 0.5
__device__ __forceinline__ float sigm(float x) {
    float t;
    asm("tanh.approx.f32 %0, %1;" : "=f"(t) : "f"(x * 0.5f));
    return fmaf(0.5f, t, 0.5f);
}

__device__ __forceinline__ bool find_chunk(int b, int NT, int& t, int& rowstart, int& cnt) {
    int cb = 0;
#pragma unroll
    for (int tt = 0; tt < TT; tt++) {
        int lo = g_base[tt], hi = g_base[tt + 1];
        int ch = (hi - lo + NT - 1) / NT;
        if (b >= cb && b < cb + ch) {
            t = tt;
            rowstart = lo + (b - cb) * NT;
            cnt = min(NT, hi - rowstart);
            return true;
        }
        cb += ch;
    }
    return false;
}

// ---------------- launch 1: histogram (g_cnt zeroed by previous replay's scatter) ----------------
__global__ void k_part1(const int* __restrict__ type_id) {
    __shared__ int sc[TT];
    if (threadIdx.x < TT) sc[threadIdx.x] = 0;
    __syncthreads();
    int i = blockIdx.x * 256 + threadIdx.x;
    int4 v = ((const int4*)type_id)[i];
    atomicAdd(&sc[v.x], 1);
    atomicAdd(&sc[v.y], 1);
    atomicAdd(&sc[v.z], 1);
    atomicAdd(&sc[v.w], 1);
    __syncthreads();
    if (threadIdx.x < TT) atomicAdd(&g_cnt[threadIdx.x], sc[threadIdx.x]);
}

// ---------------- launch 2: scatter + flag-zero + state publish/reset ----------------
__global__ void k_scatter(const int* __restrict__ type_id) {
    __shared__ int w_off[8][TT];
    __shared__ int blk_base[TT];

    // zero g_flag for the upcoming k_main (grid covers GRID_F)
    int gi = blockIdx.x * 256 + threadIdx.x;
    if (gi < GRID_F) g_flag[gi] = 0;

    // inline type-prefix from g_cnt
    int base[TT + 1];
    {
        int b = 0;
#pragma unroll
        for (int t = 0; t < TT; t++) { base[t] = b; b += g_cnt[t]; }
        base[TT] = b;
    }

    int n = blockIdx.x * 256 + threadIdx.x;
    int t = type_id[n];
    int w = threadIdx.x >> 5, lane = threadIdx.x & 31;
    int rank = 0;
#pragma unroll
    for (int tt = 0; tt < TT; tt++) {
        unsigned bm = __ballot_sync(0xffffffffu, t == tt);
        if (lane == 0) w_off[w][tt] = __popc(bm);
        if (t == tt) rank = __popc(bm & ((1u << lane) - 1));
    }
    __syncthreads();
    if (threadIdx.x < TT) {
        int tt = threadIdx.x, s = 0;
#pragma unroll
        for (int ww = 0; ww < 8; ww++) { int v = w_off[ww][tt]; w_off[ww][tt] = s; s += v; }
        blk_base[tt] = base[tt] + atomicAdd(&g_cursor[tt], s);
    }
    __syncthreads();
    g_sorted[blk_base[t] + w_off[w][t] + rank] = n;

    // ticket: last block publishes g_base and resets g_cnt/g_cursor for next replay.
    __syncthreads();
    if (threadIdx.x == 0) {
        __threadfence();
        if (atomicAdd(&g_scat_done, 1) == SCAT_BLOCKS - 1) {
#pragma unroll
            for (int tt = 0; tt <= TT; tt++) g_base[tt] = base[tt];
#pragma unroll
            for (int tt = 0; tt < TT; tt++) { g_cnt[tt] = 0; g_cursor[tt] = 0; }
            g_scat_done = 0;
            __threadfence();
        }
    }
}

// ---------------- forget role ----------------
__device__ __forceinline__ void forget_role(
    int fb, char* smem, uint32_t sb, int tid, int wid, int lane,
    const float* __restrict__ h, const float* __restrict__ c,
    const float* __restrict__ f_input, const float* __restrict__ U_f,
    const float* __restrict__ b_f, float* __restrict__ out)
{
    int t, rowstart, cnt;
    if (!find_chunk(fb, NTF, t, rowstart, cnt)) return;

    int* sh_node = (int*)(smem + F_NODE);
    float* sbf = (float*)(smem + F_BF);
    if (tid < NTF) sh_node[tid] = g_sorted[rowstart + min(tid, cnt - 1)];
    if (tid >= 128) sbf[tid - 128] = b_f[t * HH + (tid - 128)];
    __syncthreads();

    const int node0 = wid * 2, node1 = node0 + 1;
    const int nd0 = sh_node[node0], nd1 = sh_node[node1];

    // L2 prefetch for this warp's epilogue streams.
    {
        const float* cA = c + (size_t)nd0 * KK * HH;
        const float* cB = c + (size_t)nd1 * KK * HH;
        pf_l2(cA + lane * 32);
        pf_l2(cB + lane * 32);
        if (lane < 4) {
            pf_l2(f_input + (size_t)nd0 * HH + lane * 32);
            pf_l2(f_input + (size_t)nd1 * HH + lane * 32);
        }
    }

    // A loader + fp16 hsum.
#pragma unroll
    for (int i = 0; i < 2; i++) {
        int task = tid + 256 * i;
        int j4 = task & 31, n = task >> 5;
        int nd = sh_node[n];
        float4 s = make_float4(0.f, 0.f, 0.f, 0.f);
#pragma unroll
        for (int ch = 0; ch < KK; ch++) {
            float4 v = *(const float4*)&h[((size_t)nd * KK + ch) * HH + j4 * 4];
            s.x += v.x; s.y += v.y; s.z += v.z; s.w += v.w;
            *(uint2*)(smem + F_A + (n * KK + ch) * ROWB + j4 * 8) =
                make_uint2(h2u(v.x, v.y), h2u(v.z, v.w));
        }
        *(uint2*)&g_hsum[(size_t)nd * HH + j4 * 4] = make_uint2(h2u(s.x, s.y), h2u(s.z, s.w));
    }
    // B loader: B[k][n] from U_f[t][k][n].
#pragma unroll
    for (int i = 0; i < 16; i++) {
        int task = tid + 256 * i;
        int n4 = task & 31, k = task >> 5;
        float4 v = *(const float4*)&U_f[(size_t)t * HH * HH + (size_t)k * HH + n4 * 4];
        *(uint2*)(smem + F_B + k * ROWB + n4 * 8) = make_uint2(h2u(v.x, v.y), h2u(v.z, v.w));
    }
    __threadfence();   // publish hsum gpu-wide before flag release
    __syncthreads();
    if (tid == 0) st_rel(&g_flag[fb], 1);

    // Preload all A fragments.
    const int m0 = wid * 16;
    const uint32_t aaddr = sb + F_A + (m0 + (lane & 15)) * ROWB + ((lane >> 4) << 4);
    uint32_t af[8][4];
#pragma unroll
    for (int ks = 0; ks < 8; ks++) ldsm4(af[ks], aaddr + ks * 32);

    const int klocal = (lane & 7) + ((lane >> 3) & 1) * 8;
    const uint32_t btaddr = sb + F_B + klocal * ROWB + (lane >> 4) * 16;

    const int child = lane >> 2, q = lane & 3;
    const float* c0p = c + ((size_t)nd0 * KK + child) * HH;
    const float* c1p = c + ((size_t)nd1 * KK + child) * HH;
    const float* f0p = f_input + (size_t)nd0 * HH;
    const float* f1p = f_input + (size_t)nd1 * HH;

#pragma unroll 1
    for (int nb = 0; nb < 8; nb++) {
        const int colbase = nb * 16 + 2 * q;
        float2 cv00 = *(const float2*)(c0p + colbase);
        float2 cv01 = *(const float2*)(c0p + colbase + 8);
        float2 cv10 = *(const float2*)(c1p + colbase);
        float2 cv11 = *(const float2*)(c1p + colbase + 8);
        float2 f00 = *(const float2*)(f0p + colbase);
        float2 f01 = *(const float2*)(f0p + colbase + 8);
        float2 f10 = *(const float2*)(f1p + colbase);
        float2 f11 = *(const float2*)(f1p + colbase + 8);

        float acc0[4] = {0.f, 0.f, 0.f, 0.f};
        float acc1[4] = {0.f, 0.f, 0.f, 0.f};
#pragma unroll
        for (int ks = 0; ks < 8; ks++) {
            uint32_t bf4[4];
            ldsm4t(bf4, btaddr + ks * 16 * ROWB + nb * 32);
            mma16(acc0, af[ks], bf4[0], bf4[1]);
            mma16(acc1, af[ks], bf4[2], bf4[3]);
        }

        float2 bf0 = *(float2*)&sbf[colbase];
        float2 bf1 = *(float2*)&sbf[colbase + 8];

        float v00 = sigm(acc0[0] + f00.x + bf0.x) * cv00.x;
        float v01 = sigm(acc0[1] + f00.y + bf0.y) * cv00.y;
        float v10 = sigm(acc0[2] + f10.x + bf0.x) * cv10.x;
        float v11 = sigm(acc0[3] + f10.y + bf0.y) * cv10.y;
        float w00 = sigm(acc1[0] + f01.x + bf1.x) * cv01.x;
        float w01 = sigm(acc1[1] + f01.y + bf1.y) * cv01.y;
        float w10 = sigm(acc1[2] + f11.x + bf1.x) * cv11.x;
        float w11 = sigm(acc1[3] + f11.y + bf1.y) * cv11.y;
#pragma unroll
        for (int d = 4; d < 32; d <<= 1) {
            v00 += __shfl_xor_sync(0xffffffffu, v00, d);
            v01 += __shfl_xor_sync(0xffffffffu, v01, d);
            v10 += __shfl_xor_sync(0xffffffffu, v10, d);
            v11 += __shfl_xor_sync(0xffffffffu, v11, d);
            w00 += __shfl_xor_sync(0xffffffffu, w00, d);
            w01 += __shfl_xor_sync(0xffffffffu, w01, d);
            w10 += __shfl_xor_sync(0xffffffffu, w10, d);
            w11 += __shfl_xor_sync(0xffffffffu, w11, d);
        }
        if (lane < 4 && node0 < cnt) {
            *(float2*)&out[(size_t)nd0 * 512 + 384 + nb * 16 + 2 * lane] = make_float2(v00, v01);
            *(float2*)&out[(size_t)nd0 * 512 + 384 + nb * 16 + 8 + 2 * lane] = make_float2(w00, w01);
        }
        if (lane >= 4 && lane < 8 && node1 < cnt) {
            *(float2*)&out[(size_t)nd1 * 512 + 384 + nb * 16 + 2 * (lane - 4)] = make_float2(v10, v11);
            *(float2*)&out[(size_t)nd1 * 512 + 384 + nb * 16 + 8 + 2 * (lane - 4)] = make_float2(w10, w11);
        }
    }
}

// ---------------- iou role ----------------
__device__ __forceinline__ void iou_role(
    int ib, char* smem, uint32_t sb, int tid, int wid, int lane,
    const float* __restrict__ U_iou, const float* __restrict__ b_iou,
    float* __restrict__ out)
{
    int t, rowstart, cnt;
    if (!find_chunk(ib, NTI, t, rowstart, cnt)) return;

    // Wait for producing forget chunks.
    {
        int cbF = 0;
#pragma unroll
        for (int tt = 0; tt < TT; tt++) {
            if (tt == t) break;
            cbF += (g_base[tt + 1] - g_base[tt] + NTF - 1) / NTF;
        }
        int lo = g_base[t];
        int bstart = cbF + (rowstart - lo) / NTF;
        int bend = cbF + (rowstart + cnt - 1 - lo) / NTF;
        if (tid <= bend - bstart) {
            const int* fp = &g_flag[bstart + tid];
            while (ld_acq(fp) == 0) { __nanosleep(64); }
        }
    }
    __syncthreads();

    int* sh_node = (int*)(smem + I_NODE);
    float* bst = (float*)(smem + I_BST);
    if (tid < 64) sh_node[tid] = g_sorted[rowstart + min(tid, cnt - 1)];
    if (tid < 128) {
        bst[tid] = b_iou[t * 384 + tid];
        bst[128 + tid] = b_iou[t * 384 + 128 + tid];
        bst[256 + tid] = b_iou[t * 384 + 256 + tid];
    }
    __syncthreads();

    // A loader: [64 m][128 k] straight fp16 copy from g_hsum.
#pragma unroll
    for (int i = 0; i < 4; i++) {
        int task = tid + 256 * i;
        int m = task >> 4, j8 = task & 15;
        uint4 v = __ldcg((const uint4*)&g_hsum[(size_t)sh_node[m] * HH + j8 * 8]);
        *(uint4*)(smem + I_A + m * ROWB + j8 * 16) = v;
    }
    __syncthreads();

    const int m0 = (wid >> 1) * 16;
    const int nh = wid & 1;
    const uint32_t aaddr = sb + I_A + (m0 + (lane & 15)) * ROWB + ((lane >> 4) << 4);
    uint32_t af[8][4];
#pragma unroll
    for (int ks = 0; ks < 8; ks++) ldsm4(af[ks], aaddr + ks * 32);

    const int klocal = (lane & 7) + ((lane >> 3) & 1) * 8;
    const uint32_t btaddr = sb + I_B + klocal * ROWB + (lane >> 4) * 16 + nh * 128;
    const int r0 = m0 + (lane >> 2), r1 = r0 + 8;
    const int q = lane & 3;
    const int nr0 = sh_node[r0], nr1 = sh_node[r1];

    for (int nc = 0; nc < 3; nc++) {
        if (nc > 0) __syncthreads();
#pragma unroll
        for (int i = 0; i < 16; i++) {
            int task = tid + 256 * i;
            int n4 = task & 31, k = task >> 5;
            float4 v = *(const float4*)&U_iou[(size_t)t * HH * 384 + (size_t)k * 384 + nc * 128 + n4 * 4];
            *(uint2*)(smem + I_B + k * ROWB + n4 * 8) = make_uint2(h2u(v.x, v.y), h2u(v.z, v.w));
        }
        __syncthreads();

#pragma unroll 1
        for (int nb = 0; nb < 4; nb++) {
            float acc0[4] = {0.f, 0.f, 0.f, 0.f};
            float acc1[4] = {0.f, 0.f, 0.f, 0.f};
#pragma unroll
            for (int ks = 0; ks < 8; ks++) {
                uint32_t bf4[4];
                ldsm4t(bf4, btaddr + ks * 16 * ROWB + nb * 32);
                mma16(acc0, af[ks], bf4[0], bf4[1]);
                mma16(acc1, af[ks], bf4[2], bf4[3]);
            }
            const int colbase = nh * 64 + nb * 16 + 2 * q;
            float2 b20 = *(float2*)&bst[nc * 128 + colbase];
            float2 b21 = *(float2*)&bst[nc * 128 + colbase + 8];
            if (r0 < cnt) {
                *(float2*)&out[(size_t)nr0 * 512 + nc * 128 + colbase] =
                    make_float2(acc0[0] + b20.x, acc0[1] + b20.y);
                *(float2*)&out[(size_t)nr0 * 512 + nc * 128 + colbase + 8] =
                    make_float2(acc1[0] + b21.x, acc1[1] + b21.y);
            }
            if (r1 < cnt) {
                *(float2*)&out[(size_t)nr1 * 512 + nc * 128 + colbase] =
                    make_float2(acc0[2] + b20.x, acc0[3] + b20.y);
                *(float2*)&out[(size_t)nr1 * 512 + nc * 128 + colbase + 8] =
                    make_float2(acc1[2] + b21.x, acc1[3] + b21.y);
            }
        }
    }
}

// ---------------- launch 3: merged kernel (unchanged hot path) ----------------
__global__ __launch_bounds__(256, 3) void k_main(
    const float* __restrict__ h, const float* __restrict__ c,
    const float* __restrict__ f_input,
    const float* __restrict__ U_iou, const float* __restrict__ b_iou,
    const float* __restrict__ U_f, const float* __restrict__ b_f,
    float* __restrict__ out)
{
    extern __shared__ __align__(1024) char smem[];
    const uint32_t sb = smem_u32(smem);
    const int tid = threadIdx.x, wid = tid >> 5, lane = tid & 31;
    if (blockIdx.x < GRID_F)
        forget_role(blockIdx.x, smem, sb, tid, wid, lane, h, c, f_input, U_f, b_f, out);
    else
        iou_role(blockIdx.x - GRID_F, smem, sb, tid, wid, lane, U_iou, b_iou, out);
}

// ---------------- launch ----------------
extern "C" void kernel_launch(void* const* d_in, const int* in_sizes, int n_in,
                              void* d_out, int out_size) {
    const float* h       = (const float*)d_in[0];
    const float* c       = (const float*)d_in[1];
    const float* f_input = (const float*)d_in[2];
    const int*   type_id = (const int*)d_in[3];
    const float* U_iou   = (const float*)d_in[4];
    const float* b_iou   = (const float*)d_in[5];
    const float* U_f     = (const float*)d_in[6];
    const float* b_f     = (const float*)d_in[7];
    float* out = (float*)d_out;

    static int attr_done = 0;
    if (!attr_done) {
        cudaFuncSetAttribute(k_main, cudaFuncAttributeMaxDynamicSharedMemorySize, F_SMEM);
        attr_done = 1;
    }

    k_part1<<<NN / 1024, 256>>>(type_id);
    k_scatter<<<SCAT_BLOCKS, 256>>>(type_id);
    k_main<<<GRID_F + GRID_I, 256, F_SMEM>>>(h, c, f_input, U_iou, b_iou, U_f, b_f, out);
}